// round 13
// baseline (speedup 1.0000x reference)
#include <cuda_runtime.h>

#define BATCH 4096
#define SEQT  256
#define DIN   32
#define HID   64
#define GATES 256
#define BT    16          // batch rows per CTA (2 CTAs co-resident per SM)
#define NTHR  256
#define NCTA  (BATCH / BT)   // 256
#define ST    18          // padded row stride (16 rows + 2 pad)

typedef unsigned long long u64;

// ---- gate-quad weight layout W[k][u2][g][upar]: n = g*64 + u2*2 + up (R9-proven) ----
__device__ __align__(16) float g_W0q[HID * GATES];     // Whh0 quad (per-step LDG)
__device__ __align__(16) float g_Wx0q[DIN * GATES];    // Wih0 quad (per-step LDG)
__device__ __align__(16) float g_W1q[2 * HID * GATES]; // [Wih1; Whh1] quad (Wih1 LDG, Whh1 smem)
__device__ __align__(16) float g_b0q[GATES];
__device__ __align__(16) float g_b1q[GATES];

__global__ void prep_kernel(const float* __restrict__ Wih0, const float* __restrict__ Whh0,
                            const float* __restrict__ bih0, const float* __restrict__ bhh0,
                            const float* __restrict__ Wih1, const float* __restrict__ Whh1,
                            const float* __restrict__ bih1, const float* __restrict__ bhh1)
{
    int idx = blockIdx.x * blockDim.x + threadIdx.x;
    int stride = gridDim.x * blockDim.x;
    for (int j = idx; j < HID * GATES; j += stride) {
        int k = j / GATES, r = j % GATES;
        int n = ((r >> 1) & 3) * HID + (r >> 3) * 2 + (r & 1);
        g_W0q[j] = Whh0[n * HID + k];
    }
    for (int j = idx; j < DIN * GATES; j += stride) {
        int k = j / GATES, r = j % GATES;
        int n = ((r >> 1) & 3) * HID + (r >> 3) * 2 + (r & 1);
        g_Wx0q[j] = Wih0[n * DIN + k];
    }
    for (int j = idx; j < 2 * HID * GATES; j += stride) {
        int k = j / GATES, r = j % GATES;
        int n = ((r >> 1) & 3) * HID + (r >> 3) * 2 + (r & 1);
        g_W1q[j] = (k < HID) ? Wih1[n * HID + k] : Whh1[n * HID + (k - HID)];
    }
    for (int r = idx; r < GATES; r += stride) {
        int n = ((r >> 1) & 3) * HID + (r >> 3) * 2 + (r & 1);
        g_b0q[r] = bih0[n] + bhh0[n];
        g_b1q[r] = bih1[n] + bhh1[n];
    }
}

// ---- packed f32x2 helpers ----
__device__ __forceinline__ u64 fma2(u64 a, u64 b, u64 c) {
    u64 d;
    asm("fma.rn.f32x2 %0, %1, %2, %3;" : "=l"(d) : "l"(a), "l"(b), "l"(c));
    return d;
}
__device__ __forceinline__ u64 dup2(float x) {
    u64 d;
    asm("mov.b64 %0, {%1, %1};" : "=l"(d) : "f"(x));
    return d;
}
__device__ __forceinline__ float2 unpack2(u64 v) {
    float2 f;
    asm("mov.b64 {%0, %1}, %2;" : "=f"(f.x), "=f"(f.y) : "l"(v));
    return f;
}

// ---- fast activations (MUFU EX2/RCP, proven ~2.5e-7 end-to-end) ----
__device__ __forceinline__ float fast_ex2(float x) {
    float y; asm("ex2.approx.f32 %0, %1;" : "=f"(y) : "f"(x)); return y;
}
__device__ __forceinline__ float fast_rcp(float x) {
    float y; asm("rcp.approx.f32 %0, %1;" : "=f"(y) : "f"(x)); return y;
}
__device__ __forceinline__ float sigf(float x) {
    return fast_rcp(1.0f + fast_ex2(-1.4426950408889634f * x));
}
__device__ __forceinline__ float tanhf_fast(float x) {
    x = fminf(fmaxf(x, -15.0f), 15.0f);
    float e = fast_ex2(-2.8853900817779268f * x);
    return (1.0f - e) * fast_rcp(1.0f + e);
}

// GEMM fragment (quad layout): 2 rows x 8 gate-cols; per k: 1 LDS.64 act + 2 x.128 weights
template <bool GW, int K>
__device__ __forceinline__ void gemm_q2(const float* __restrict__ aT,
                                        const float* __restrict__ Wq,
                                        int m0, int w8, u64 acc[2][4])
{
#pragma unroll 4
    for (int k = 0; k < K; k++) {
        float2 hv = *(const float2*)(aT + k * ST + m0);
        const float* wp = Wq + k * GATES + w8;
        ulonglong2 wv0, wv1;
        if (GW) {
            wv0 = __ldg((const ulonglong2*)wp);
            wv1 = __ldg((const ulonglong2*)(wp + 4));
        } else {
            wv0 = *(const ulonglong2*)wp;
            wv1 = *(const ulonglong2*)(wp + 4);
        }
        u64 a0 = dup2(hv.x);
        acc[0][0] = fma2(a0, wv0.x, acc[0][0]);
        acc[0][1] = fma2(a0, wv0.y, acc[0][1]);
        acc[0][2] = fma2(a0, wv1.x, acc[0][2]);
        acc[0][3] = fma2(a0, wv1.y, acc[0][3]);
        u64 a1 = dup2(hv.y);
        acc[1][0] = fma2(a1, wv0.x, acc[1][0]);
        acc[1][1] = fma2(a1, wv0.y, acc[1][1]);
        acc[1][2] = fma2(a1, wv1.x, acc[1][2]);
        acc[1][3] = fma2(a1, wv1.y, acc[1][3]);
    }
}

__device__ __forceinline__ void acc_init2(const float* __restrict__ sB, int w8, u64 acc[2][4])
{
    ulonglong2 b0 = *(const ulonglong2*)(sB + w8);
    ulonglong2 b1 = *(const ulonglong2*)(sB + w8 + 4);
    acc[0][0] = b0.x; acc[0][1] = b0.y; acc[0][2] = b1.x; acc[0][3] = b1.y;
    acc[1][0] = b0.x; acc[1][1] = b0.y; acc[1][2] = b1.x; acc[1][3] = b1.y;
}

// update 2 rows x 2 cells; quad acc: acc[r][g] packs cells (u0,u0+1) of gate g
__device__ __forceinline__ void lstm_update2(const u64 acc[2][4], float c[2][2],
                                             float* __restrict__ hT, int m0, int u0)
{
    float h[2][2];
#pragma unroll
    for (int r = 0; r < 2; r++) {
        float2 pi = unpack2(acc[r][0]);
        float2 pf = unpack2(acc[r][1]);
        float2 pg = unpack2(acc[r][2]);
        float2 po = unpack2(acc[r][3]);
        {
            float iv = sigf(pi.x), fv = sigf(pf.x), gv = tanhf_fast(pg.x), ov = sigf(po.x);
            float cc = fv * c[r][0] + iv * gv;
            c[r][0] = cc;
            h[r][0] = ov * tanhf_fast(cc);
        }
        {
            float iv = sigf(pi.y), fv = sigf(pf.y), gv = tanhf_fast(pg.y), ov = sigf(po.y);
            float cc = fv * c[r][1] + iv * gv;
            c[r][1] = cc;
            h[r][1] = ov * tanhf_fast(cc);
        }
    }
    *(float2*)(hT + (u0 + 0) * ST + m0) = make_float2(h[0][0], h[1][0]);
    *(float2*)(hT + (u0 + 1) * ST + m0) = make_float2(h[0][1], h[1][1]);
}

// Shared layout (floats) — fits 2 CTAs/SM (79 KB each)
#define OFF_WB   0                            // Whh1 quad (16384)
#define OFF_B0   (OFF_WB + HID * GATES)
#define OFF_B1   (OFF_B0 + GATES)
#define OFF_H0T  (OFF_B1 + GATES)
#define OFF_H1T  (OFF_H0T + HID * ST)
#define OFF_XT   (OFF_H1T + HID * ST)
#define SMEM_FLOATS (OFF_XT + DIN * ST)       // 19776 floats = 79104 B

__global__ void __launch_bounds__(NTHR, 2)
lstm_fused(const float* __restrict__ x,
           const float* __restrict__ W1h, const float* __restrict__ b1h,
           const float* __restrict__ W2h, const float* __restrict__ b2h,
           float* __restrict__ out)
{
    extern __shared__ float sm[];
    float* sWB = sm + OFF_WB;      // Whh1 quad (smem, used in P1)
    float* sB0 = sm + OFF_B0;
    float* sB1 = sm + OFF_B1;
    float* h0T = sm + OFF_H0T;
    float* h1T = sm + OFF_H1T;
    float* xT  = sm + OFF_XT;

    const int tid = threadIdx.x;
    const int b0  = blockIdx.x * BT;

    // stage Whh1 + biases; zero states
    for (int i = tid; i < HID * GATES / 4; i += NTHR)
        ((float4*)sWB)[i] = ((const float4*)(g_W1q + HID * GATES))[i];
    if (tid < GATES) { sB0[tid] = g_b0q[tid]; sB1[tid] = g_b1q[tid]; }
    for (int i = tid; i < 2 * HID * ST; i += NTHR) h0T[i] = 0.0f;  // h0T+h1T contiguous

    // thread tile: rows m0,m0+1 (16 rows total); cells u0,u0+1 (quad block w8)
    const int gm = tid & 7;
    const int gn = tid >> 3;        // 0..31
    const int m0 = gm * 2;
    const int u0 = gn * 2;
    const int w8 = gn * 8;

    float c0[2][2] = {{0.f, 0.f}, {0.f, 0.f}};
    float c1[2][2] = {{0.f, 0.f}, {0.f, 0.f}};
    u64 acc0[2][4], acc1[2][4];

    // x staging: 16 rows x 16 float2-chunks
    const int xm = tid >> 4;        // 0..15
    const int xd = tid & 15;        // 0..15
    const float* xrow = x + (size_t)(b0 + xm) * SEQT * DIN + xd * 2;

    // prologue: stage x(0); acc0 = b0 + Wih0*x(0)  (h0(-1)=0)
    float2 xv = *(const float2*)(xrow);
    xT[(2 * xd + 0) * ST + xm] = xv.x;
    xT[(2 * xd + 1) * ST + xm] = xv.y;
    __syncthreads();

    acc_init2(sB0, w8, acc0);
    gemm_q2<true, DIN>(xT, g_Wx0q, m0, w8, acc0);
    xv = *(const float2*)(xrow + DIN);       // x(1)
    __syncthreads();                         // xT readers done before restage

    for (int t = 0; t < SEQT; t++) {
        // ---- P1: update0(t) (MUFU) || Whh1*h1(t-1) (smem FFMA) + stage x(t+1)
        lstm_update2(acc0, c0, h0T, m0, u0);              // writes h0(t)
        acc_init2(sB1, w8, acc1);
        gemm_q2<false, HID>(h1T, sWB, m0, w8, acc1);      // Whh1*h1(t-1)
        xT[(2 * xd + 0) * ST + xm] = xv.x;                // stage x(t+1)
        xT[(2 * xd + 1) * ST + xm] = xv.y;
        {
            int tn = (t + 2 < SEQT) ? t + 2 : SEQT - 1;
            xv = *(const float2*)(xrow + (size_t)tn * DIN);
        }
        __syncthreads();                                  // B1: h0(t), x(t+1) visible

        // ---- P2: Wih1*h0(t) (L2) + Whh0[0:32]*h0(t) (L2) + Wih0*x(t+1) (L2)
        gemm_q2<true, HID>(h0T, g_W1q, m0, w8, acc1);     // Wih1*h0(t)
        acc_init2(sB0, w8, acc0);
        gemm_q2<true, 32>(h0T, g_W0q, m0, w8, acc0);      // Whh0 k:0..31
        gemm_q2<true, DIN>(xT, g_Wx0q, m0, w8, acc0);     // Wih0*x(t+1)

        // ---- P3 (no barrier): Whh0[32:64] (L2 FFMA) || update1(t) (MUFU)
        gemm_q2<true, 32>(h0T + 32 * ST, g_W0q + 32 * GATES, m0, w8, acc0);
        lstm_update2(acc1, c1, h1T, m0, u0);              // writes h1(t)
        __syncthreads();                                  // B2: h1(t) visible
    }

    // ---- head: out[m] = b2 + sum_n W2[n]*relu(b1[n] + sum_k h1(k,m) W1[n,k]) ----
    {
        int m = tid >> 4;      // 0..15
        int q = tid & 15;      // 0..15
        float pm = 0.0f;
#pragma unroll
        for (int jj = 0; jj < 4; jj++) {
            int n = q * 4 + jj;
            float sv = b1h[n];
#pragma unroll 8
            for (int k = 0; k < HID; k++)
                sv += h1T[k * ST + m] * W1h[n * HID + k];
            pm += fmaxf(sv, 0.0f) * W2h[n];
        }
#pragma unroll
        for (int off = 8; off > 0; off >>= 1)
            pm += __shfl_down_sync(0xffffffffu, pm, off, 16);
        if (q == 0) out[b0 + m] = pm + b2h[0];
    }
}

extern "C" void kernel_launch(void* const* d_in, const int* in_sizes, int n_in,
                              void* d_out, int out_size)
{
    const float* x    = (const float*)d_in[0];
    const float* Wih0 = (const float*)d_in[1];
    const float* Whh0 = (const float*)d_in[2];
    const float* bih0 = (const float*)d_in[3];
    const float* bhh0 = (const float*)d_in[4];
    const float* Wih1 = (const float*)d_in[5];
    const float* Whh1 = (const float*)d_in[6];
    const float* bih1 = (const float*)d_in[7];
    const float* bhh1 = (const float*)d_in[8];
    const float* W1   = (const float*)d_in[9];
    const float* b1   = (const float*)d_in[10];
    const float* W2   = (const float*)d_in[11];
    const float* b2   = (const float*)d_in[12];

    prep_kernel<<<64, 256>>>(Wih0, Whh0, bih0, bhh0, Wih1, Whh1, bih1, bhh1);

    size_t smem_bytes = (size_t)SMEM_FLOATS * sizeof(float);   // 79104 B
    cudaFuncSetAttribute(lstm_fused,
                         cudaFuncAttributeMaxDynamicSharedMemorySize, (int)smem_bytes);
    lstm_fused<<<NCTA, NTHR, smem_bytes>>>(x, W1, b1, W2, b2, (float*)d_out);
}

// round 14
// speedup vs baseline: 1.6606x; 1.6606x over previous
#include <cuda_runtime.h>

#define BATCH 4096
#define SEQT  256
#define DIN   32
#define HID   64
#define GATES 256
#define BT    32
#define NTHR  256
#define NCTA  128
#define ST    36    // padded row stride (floats) for transposed activation buffers

typedef unsigned long long u64;

// ---- gate-quad weight layout W[k][u2][g][upar]: n = g*64 + u2*2 + up (R9-proven) ----
__device__ __align__(16) float g_W0q[HID * GATES];     // Whh0 quad [64][256]
__device__ __align__(16) float g_Wx0q[DIN * GATES];    // Wih0 quad [32][256] (per-step LDG)
__device__ __align__(16) float g_W1q[2 * HID * GATES]; // [Wih1; Whh1] quad [128][256]
__device__ __align__(16) float g_b0q[GATES];
__device__ __align__(16) float g_b1q[GATES];

__global__ void prep_kernel(const float* __restrict__ Wih0, const float* __restrict__ Whh0,
                            const float* __restrict__ bih0, const float* __restrict__ bhh0,
                            const float* __restrict__ Wih1, const float* __restrict__ Whh1,
                            const float* __restrict__ bih1, const float* __restrict__ bhh1)
{
    int idx = blockIdx.x * blockDim.x + threadIdx.x;
    int stride = gridDim.x * blockDim.x;
    for (int j = idx; j < HID * GATES; j += stride) {
        int k = j / GATES, r = j % GATES;
        int n = ((r >> 1) & 3) * HID + (r >> 3) * 2 + (r & 1);
        g_W0q[j] = Whh0[n * HID + k];
    }
    for (int j = idx; j < DIN * GATES; j += stride) {
        int k = j / GATES, r = j % GATES;
        int n = ((r >> 1) & 3) * HID + (r >> 3) * 2 + (r & 1);
        g_Wx0q[j] = Wih0[n * DIN + k];
    }
    for (int j = idx; j < 2 * HID * GATES; j += stride) {
        int k = j / GATES, r = j % GATES;
        int n = ((r >> 1) & 3) * HID + (r >> 3) * 2 + (r & 1);
        g_W1q[j] = (k < HID) ? Wih1[n * HID + k] : Whh1[n * HID + (k - HID)];
    }
    for (int r = idx; r < GATES; r += stride) {
        int n = ((r >> 1) & 3) * HID + (r >> 3) * 2 + (r & 1);
        g_b0q[r] = bih0[n] + bhh0[n];
        g_b1q[r] = bih1[n] + bhh1[n];
    }
}

// ---- packed f32x2 helpers ----
__device__ __forceinline__ u64 fma2(u64 a, u64 b, u64 c) {
    u64 d;
    asm("fma.rn.f32x2 %0, %1, %2, %3;" : "=l"(d) : "l"(a), "l"(b), "l"(c));
    return d;
}
__device__ __forceinline__ u64 dup2(float x) {
    u64 d;
    asm("mov.b64 %0, {%1, %1};" : "=l"(d) : "f"(x));
    return d;
}
__device__ __forceinline__ float2 unpack2(u64 v) {
    float2 f;
    asm("mov.b64 {%0, %1}, %2;" : "=f"(f.x), "=f"(f.y) : "l"(v));
    return f;
}

// ---- fast activations (MUFU EX2/RCP, proven ~2.5e-7 end-to-end) ----
__device__ __forceinline__ float fast_ex2(float x) {
    float y; asm("ex2.approx.f32 %0, %1;" : "=f"(y) : "f"(x)); return y;
}
__device__ __forceinline__ float fast_rcp(float x) {
    float y; asm("rcp.approx.f32 %0, %1;" : "=f"(y) : "f"(x)); return y;
}
__device__ __forceinline__ float sigf(float x) {
    return fast_rcp(1.0f + fast_ex2(-1.4426950408889634f * x));
}
__device__ __forceinline__ float tanhf_fast(float x) {
    x = fminf(fmaxf(x, -15.0f), 15.0f);
    float e = fast_ex2(-2.8853900817779268f * x);  // exp(-2x)
    return (1.0f - e) * fast_rcp(1.0f + e);
}

// GEMM fragment, quad layout: per k: 1 LDS.128 act (4 rows) + 2 LDS.128 weights (8 cols),
// 4 dup2, 16 FFMA2. acc[r][g] = f32x2 over cells (u0,u0+1), gate g, row m0+r.
template <bool GW, int K>
__device__ __forceinline__ void gemm_q4(const float* __restrict__ aT,
                                        const float* __restrict__ Wq,
                                        int m0, int w8, u64 acc[4][4])
{
#pragma unroll 8
    for (int k = 0; k < K; k++) {
        float4 hv = *(const float4*)(aT + k * ST + m0);
        const float* wp = Wq + k * GATES + w8;
        ulonglong2 wv0, wv1;
        if (GW) {
            wv0 = __ldg((const ulonglong2*)wp);       // gates i,f (cells u0,u0+1)
            wv1 = __ldg((const ulonglong2*)(wp + 4)); // gates g,o
        } else {
            wv0 = *(const ulonglong2*)wp;
            wv1 = *(const ulonglong2*)(wp + 4);
        }
        u64 a;
        a = dup2(hv.x);
        acc[0][0] = fma2(a, wv0.x, acc[0][0]);
        acc[0][1] = fma2(a, wv0.y, acc[0][1]);
        acc[0][2] = fma2(a, wv1.x, acc[0][2]);
        acc[0][3] = fma2(a, wv1.y, acc[0][3]);
        a = dup2(hv.y);
        acc[1][0] = fma2(a, wv0.x, acc[1][0]);
        acc[1][1] = fma2(a, wv0.y, acc[1][1]);
        acc[1][2] = fma2(a, wv1.x, acc[1][2]);
        acc[1][3] = fma2(a, wv1.y, acc[1][3]);
        a = dup2(hv.z);
        acc[2][0] = fma2(a, wv0.x, acc[2][0]);
        acc[2][1] = fma2(a, wv0.y, acc[2][1]);
        acc[2][2] = fma2(a, wv1.x, acc[2][2]);
        acc[2][3] = fma2(a, wv1.y, acc[2][3]);
        a = dup2(hv.w);
        acc[3][0] = fma2(a, wv0.x, acc[3][0]);
        acc[3][1] = fma2(a, wv0.y, acc[3][1]);
        acc[3][2] = fma2(a, wv1.x, acc[3][2]);
        acc[3][3] = fma2(a, wv1.y, acc[3][3]);
    }
}

__device__ __forceinline__ void acc_init(const float* __restrict__ sB, int w8, u64 acc[4][4])
{
    ulonglong2 b0 = *(const ulonglong2*)(sB + w8);
    ulonglong2 b1 = *(const ulonglong2*)(sB + w8 + 4);
#pragma unroll
    for (int r = 0; r < 4; r++) {
        acc[r][0] = b0.x; acc[r][1] = b0.y; acc[r][2] = b1.x; acc[r][3] = b1.y;
    }
}

// activations + cell update + write h (transposed): 4 rows x 2 cells per thread
__device__ __forceinline__ void lstm_update(const u64 acc[4][4], float* __restrict__ cr,
                                            float* __restrict__ hT, int m0, int u0)
{
    float hn0[4], hn1[4];
#pragma unroll
    for (int m = 0; m < 4; m++) {
        float2 pi = unpack2(acc[m][0]);
        float2 pf = unpack2(acc[m][1]);
        float2 pg = unpack2(acc[m][2]);
        float2 po = unpack2(acc[m][3]);
        {
            float iv = sigf(pi.x), fv = sigf(pf.x), gv = tanhf_fast(pg.x), ov = sigf(po.x);
            float c = fv * cr[m * 2 + 0] + iv * gv;
            cr[m * 2 + 0] = c;
            hn0[m] = ov * tanhf_fast(c);
        }
        {
            float iv = sigf(pi.y), fv = sigf(pf.y), gv = tanhf_fast(pg.y), ov = sigf(po.y);
            float c = fv * cr[m * 2 + 1] + iv * gv;
            cr[m * 2 + 1] = c;
            hn1[m] = ov * tanhf_fast(c);
        }
    }
    *(float4*)(hT + (u0 + 0) * ST + m0) = make_float4(hn0[0], hn0[1], hn0[2], hn0[3]);
    *(float4*)(hT + (u0 + 1) * ST + m0) = make_float4(hn1[0], hn1[1], hn1[2], hn1[3]);
}

// Shared layout (floats) — identical footprint to R7 (221696 B)
#define OFF_W0   0
#define OFF_W1   (OFF_W0 + HID * GATES)
#define OFF_B0   (OFF_W1 + 2 * HID * GATES)
#define OFF_B1   (OFF_B0 + GATES)
#define OFF_H0T  (OFF_B1 + GATES)
#define OFF_H1T  (OFF_H0T + HID * ST)
#define OFF_XT   (OFF_H1T + HID * ST)
#define SMEM_FLOATS (OFF_XT + DIN * ST)

__global__ void __launch_bounds__(NTHR, 1)
lstm_fused(const float* __restrict__ x,
           const float* __restrict__ W1h, const float* __restrict__ b1h,
           const float* __restrict__ W2h, const float* __restrict__ b2h,
           float* __restrict__ out)
{
    extern __shared__ float sm[];
    float* sW0 = sm + OFF_W0;              // Whh0 quad
    float* sW1 = sm + OFF_W1;              // [Wih1;Whh1] quad
    float* sB0 = sm + OFF_B0;
    float* sB1 = sm + OFF_B1;
    float* h0T = sm + OFF_H0T;
    float* h1T = sm + OFF_H1T;
    float* xT  = sm + OFF_XT;

    const int tid = threadIdx.x;
    const int b0  = blockIdx.x * BT;

    // stage weights + zero states
    for (int i = tid; i < HID * GATES / 4; i += NTHR)
        ((float4*)sW0)[i] = ((const float4*)g_W0q)[i];
    for (int i = tid; i < 2 * HID * GATES / 4; i += NTHR)
        ((float4*)sW1)[i] = ((const float4*)g_W1q)[i];
    if (tid < GATES) { sB0[tid] = g_b0q[tid]; sB1[tid] = g_b1q[tid]; }
    for (int i = tid; i < 2 * HID * ST; i += NTHR) h0T[i] = 0.0f;  // h0T+h1T contiguous

    // thread tile: rows m0..m0+3; cells u0,u0+1 (quad block w8)
    const int gm = tid & 7;
    const int gn = tid >> 3;
    const int m0 = gm * 4;
    const int u0 = gn * 2;
    const int w8 = gn * 8;

    float c0r[8], c1r[8];
#pragma unroll
    for (int i = 0; i < 8; i++) { c0r[i] = 0.0f; c1r[i] = 0.0f; }

    // x staging: thread -> (row xm, float4 chunk xd)
    const int xm = tid >> 3;
    const int xd = tid & 7;
    const float* xptr = x + (size_t)(b0 + xm) * SEQT * DIN + xd * 4;

    // prologue: stage x(0), acc0(0) = b0 + Wih0*x(0)  (h0(-1)=0)
    float4 xv = *(const float4*)(xptr);
    xT[(4 * xd + 0) * ST + xm] = xv.x;
    xT[(4 * xd + 1) * ST + xm] = xv.y;
    xT[(4 * xd + 2) * ST + xm] = xv.z;
    xT[(4 * xd + 3) * ST + xm] = xv.w;
    __syncthreads();

    u64 acc0[4][4], acc1[4][4];
    acc_init(sB0, w8, acc0);
    gemm_q4<true, DIN>(xT, g_Wx0q, m0, w8, acc0);
    xv = *(const float4*)(xptr + DIN);      // x(1)
    __syncthreads();                        // xT readers done before loop overwrites

    for (int t = 0; t < SEQT; t++) {
        // ---- P1: update0(t) (MUFU)  ||  Whh1*h1(t-1) (FFMA)  + stage x(t+1)
        lstm_update(acc0, c0r, h0T, m0, u0);            // writes h0(t)
        acc_init(sB1, w8, acc1);
        gemm_q4<false, HID>(h1T, sW1 + HID * GATES, m0, w8, acc1);  // Whh1*h1(t-1)
        xT[(4 * xd + 0) * ST + xm] = xv.x;              // stage x(t+1)
        xT[(4 * xd + 1) * ST + xm] = xv.y;
        xT[(4 * xd + 2) * ST + xm] = xv.z;
        xT[(4 * xd + 3) * ST + xm] = xv.w;
        {
            int tn = (t + 2 < SEQT) ? t + 2 : SEQT - 1;
            xv = *(const float4*)(xptr + (size_t)tn * DIN);  // prefetch x(t+2)
        }
        __syncthreads();                                // B1: h0(t), x(t+1) visible

        // ---- P2: Wih1*h0(t) + Whh0[0:32]*h0(t) + Wih0*x(t+1)  (pure FFMA)
        gemm_q4<false, HID>(h0T, sW1, m0, w8, acc1);    // Wih1*h0(t)
        acc_init(sB0, w8, acc0);
        gemm_q4<false, 32>(h0T, sW0, m0, w8, acc0);     // Whh0[k:0..31]
        gemm_q4<true, DIN>(xT, g_Wx0q, m0, w8, acc0);   // Wih0*x(t+1)

        // ---- P3 (no barrier): Whh0[32:64] (FFMA) || update1(t) (MUFU)
        gemm_q4<false, 32>(h0T + 32 * ST, sW0 + 32 * GATES, m0, w8, acc0); // Whh0[k:32..63]
        lstm_update(acc1, c1r, h1T, m0, u0);            // writes h1(t)
        __syncthreads();                                // B2: h1(t) visible
    }

    // ---- head: out[m] = b2 + sum_n W2[n]*relu(b1[n] + sum_k h1(k,m) W1[n,k]) ----
    {
        int m = tid >> 3;      // 0..31
        int q = tid & 7;       // 0..7
        float pm = 0.0f;
#pragma unroll
        for (int jj = 0; jj < 8; jj++) {
            int n = q * 8 + jj;
            float s = b1h[n];
#pragma unroll 8
            for (int k = 0; k < HID; k++)
                s += h1T[k * ST + m] * W1h[n * HID + k];
            pm += fmaxf(s, 0.0f) * W2h[n];
        }
#pragma unroll
        for (int off = 4; off > 0; off >>= 1)
            pm += __shfl_down_sync(0xffffffffu, pm, off, 8);
        if (q == 0) out[b0 + m] = pm + b2h[0];
    }
}

extern "C" void kernel_launch(void* const* d_in, const int* in_sizes, int n_in,
                              void* d_out, int out_size)
{
    const float* x    = (const float*)d_in[0];
    const float* Wih0 = (const float*)d_in[1];
    const float* Whh0 = (const float*)d_in[2];
    const float* bih0 = (const float*)d_in[3];
    const float* bhh0 = (const float*)d_in[4];
    const float* Wih1 = (const float*)d_in[5];
    const float* Whh1 = (const float*)d_in[6];
    const float* bih1 = (const float*)d_in[7];
    const float* bhh1 = (const float*)d_in[8];
    const float* W1   = (const float*)d_in[9];
    const float* b1   = (const float*)d_in[10];
    const float* W2   = (const float*)d_in[11];
    const float* b2   = (const float*)d_in[12];

    prep_kernel<<<64, 256>>>(Wih0, Whh0, bih0, bhh0, Wih1, Whh1, bih1, bhh1);

    size_t smem_bytes = (size_t)SMEM_FLOATS * sizeof(float);  // 221696 B
    cudaFuncSetAttribute(lstm_fused,
                         cudaFuncAttributeMaxDynamicSharedMemorySize, (int)smem_bytes);
    lstm_fused<<<NCTA, NTHR, smem_bytes>>>(x, W1, b1, W2, b2, (float*)d_out);
}